// round 11
// baseline (speedup 1.0000x reference)
#include <cuda_runtime.h>
#include <cuda_bf16.h>

#define SZ_OUT (64ull * 1024ull * 64ull)
#define STRIP 1028

// ===========================================================================
// bf16 split-GEMM helpers (mma.sync m16n8k16, 3-MMA fp32 emulation)
// 64-col bf16 tiles; chunk cb (0..7) of row r stored at chunk (cb ^ (r & 7)).
// ===========================================================================
__device__ __forceinline__ unsigned pk_bf2(float a, float b) {
    __nv_bfloat162 t = __floats2bfloat162_rn(a, b);
    return *reinterpret_cast<unsigned*>(&t);
}

__device__ __forceinline__ void split_store(__nv_bfloat16* hi, __nv_bfloat16* lo,
                                            int r, int c, float4 v)
{
    int cb  = c >> 3;
    int off = (r << 6) + ((cb ^ (r & 7)) << 3) + (c & 7);
    float hx = __bfloat162float(__float2bfloat16(v.x));
    float hy = __bfloat162float(__float2bfloat16(v.y));
    float hz = __bfloat162float(__float2bfloat16(v.z));
    float hw = __bfloat162float(__float2bfloat16(v.w));
    *(uint2*)(hi + off) = make_uint2(pk_bf2(hx, hy), pk_bf2(hz, hw));
    *(uint2*)(lo + off) = make_uint2(pk_bf2(v.x - hx, v.y - hy),
                                     pk_bf2(v.z - hz, v.w - hw));
}

__device__ __forceinline__ void ldsm4(unsigned* r, unsigned addr) {
    asm volatile("ldmatrix.sync.aligned.m8n8.x4.shared.b16 {%0,%1,%2,%3}, [%4];"
                 : "=r"(r[0]), "=r"(r[1]), "=r"(r[2]), "=r"(r[3]) : "r"(addr));
}
__device__ __forceinline__ void ldsm4t(unsigned* r, unsigned addr) {
    asm volatile("ldmatrix.sync.aligned.m8n8.x4.trans.shared.b16 {%0,%1,%2,%3}, [%4];"
                 : "=r"(r[0]), "=r"(r[1]), "=r"(r[2]), "=r"(r[3]) : "r"(addr));
}
__device__ __forceinline__ void mma_bf16(float* c, const unsigned* a, const unsigned* b) {
    asm volatile("mma.sync.aligned.m16n8k16.row.col.f32.bf16.bf16.f32 "
                 "{%0,%1,%2,%3}, {%4,%5,%6,%7}, {%8,%9}, {%0,%1,%2,%3};"
                 : "+f"(c[0]), "+f"(c[1]), "+f"(c[2]), "+f"(c[3])
                 : "r"(a[0]), "r"(a[1]), "r"(a[2]), "r"(a[3]), "r"(b[0]), "r"(b[1]));
}

__device__ __forceinline__ unsigned sw_off(int r, int cb) {
    return (unsigned)((r << 7) + (((cb ^ (r & 7))) << 4));
}

// FFMA-pipe exp for t <= 0: e^t = 2^n * 2^f, deg-5 Taylor (rel err < 2.5e-6)
__device__ __forceinline__ float fast_exp(float t) {
    float y = t * 1.4426950408889634f;
    int   n = __float2int_rn(y);
    float f = y - (float)n;
    float p = 1.3333558146428443e-3f;
    p = fmaf(p, f, 9.6181291076284772e-3f);
    p = fmaf(p, f, 5.5504108664821580e-2f);
    p = fmaf(p, f, 2.4022650695910071e-1f);
    p = fmaf(p, f, 6.9314718055994531e-1f);
    p = fmaf(p, f, 1.0f);
    int e = n + 127;
    e = e < 0 ? 0 : e;
    return p * __int_as_float(e << 23);
}

// ---------------------------------------------------------------------------
// Kernel 1: bias[b,q,k] = 0.125 * sum_d Q[b,q,d] * R_k[q,k,d]  (pre-scaled)
// ---------------------------------------------------------------------------
__global__ void __launch_bounds__(256) k_bias(const float* __restrict__ Q,
                                              const float* __restrict__ Rk,
                                              float* __restrict__ attn)
{
    const int q  = blockIdx.y;
    const int k0 = blockIdx.x << 6;
    if (k0 > q) return;

    __shared__ __align__(16) __nv_bfloat16 aHi[4096], aLo[4096], bHi[4096], bLo[4096];
    const int tid = threadIdx.x;

    #pragma unroll
    for (int i = 0; i < 4; i++) {
        int f = tid + (i << 8); int r = f >> 4, c = (f & 15) << 2;
        float4 v = *(const float4*)&Q[((size_t)r << 16) + ((size_t)q << 6) + c];
        split_store(aHi, aLo, r, c, v);
    }
    #pragma unroll
    for (int i = 0; i < 4; i++) {
        int f = tid + (i << 8); int r = f >> 4, c = (f & 15) << 2;
        float4 v = *(const float4*)&Rk[(((size_t)q << 10) + (size_t)(k0 + r)) * 64 + c];
        split_store(bHi, bLo, r, c, v);
    }
    __syncthreads();

    const int warp = tid >> 5, lane = tid & 31;
    const int wm = (warp & 3) << 4;
    const int wn = (warp >> 2) << 5;

    const unsigned aH = (unsigned)__cvta_generic_to_shared(aHi);
    const unsigned aL = (unsigned)__cvta_generic_to_shared(aLo);
    const unsigned bH = (unsigned)__cvta_generic_to_shared(bHi);
    const unsigned bL = (unsigned)__cvta_generic_to_shared(bLo);

    const int arow = wm + (lane & 15);
    const int lhi  = lane >> 4;

    float c_[4][4] = {};

    #pragma unroll
    for (int ks = 0; ks < 4; ks++) {
        const int cb = (ks << 1) + lhi;
        unsigned a_hi[4], a_lo[4];
        ldsm4(a_hi, aH + sw_off(arow, cb));
        ldsm4(a_lo, aL + sw_off(arow, cb));
        unsigned b_hi[2][4], b_lo[2][4];
        #pragma unroll
        for (int h = 0; h < 2; h++) {
            int brow = wn + (h << 4) + (lane & 15);
            ldsm4(b_hi[h], bH + sw_off(brow, cb));
            ldsm4(b_lo[h], bL + sw_off(brow, cb));
        }
        #pragma unroll
        for (int j = 0; j < 4; j++) {
            const int h = j >> 1, o = j & 1;
            unsigned bh[2] = {b_hi[h][o], b_hi[h][o + 2]};
            unsigned bl[2] = {b_lo[h][o], b_lo[h][o + 2]};
            mma_bf16(c_[j], a_hi, bh);
            mma_bf16(c_[j], a_hi, bl);
            mma_bf16(c_[j], a_lo, bh);
        }
    }

    const int row0 = wm + (lane >> 2);
    const int coll = (lane & 3) << 1;
    #pragma unroll
    for (int j = 0; j < 4; j++) {
        int col = k0 + wn + (j << 3) + coll;
        *(float2*)&attn[((size_t)row0 << 20) + ((size_t)q << 10) + col] =
            make_float2(c_[j][0] * 0.125f, c_[j][1] * 0.125f);
        *(float2*)&attn[((size_t)(row0 + 8) << 20) + ((size_t)q << 10) + col] =
            make_float2(c_[j][2] * 0.125f, c_[j][3] * 0.125f);
    }
}

// ---------------------------------------------------------------------------
// Kernel 2: per (b, 32-row q strip). 512 threads, ~200 KB smem.
// ---------------------------------------------------------------------------
__global__ void __launch_bounds__(512) k_attn(const float* __restrict__ Q,
                                              const float* __restrict__ K,
                                              const float* __restrict__ V,
                                              float* attn,
                                              float* __restrict__ out)
{
    extern __shared__ float sm[];
    float* strip = sm;                                      // [32][1028]
    __nv_bfloat16* bufs = (__nv_bfloat16*)(strip + 32 * STRIP);
    __nv_bfloat16* qHi = bufs;
    __nv_bfloat16* qLo = bufs + 2048;
    __nv_bfloat16* kHi = bufs + 4096;
    __nv_bfloat16* kLo = bufs + 20480;
    __nv_bfloat16* pHi = bufs;
    __nv_bfloat16* pLo = bufs + 4096;
    __nv_bfloat16* vHi = bufs + 8192;
    __nv_bfloat16* vLo = bufs + 16384;
    float* red = (float*)bufs;
    __shared__ float sInv[32];

    const int b   = blockIdx.x;
    const int q0  = (gridDim.y - 1 - blockIdx.y) << 5;
    const int tid = threadIdx.x;
    const int warp = tid >> 5, lane = tid & 31, lhi = lane >> 4;

    {
        int r = tid >> 4, c = (tid & 15) << 2;
        float4 v = *(const float4*)&Q[((size_t)b << 16) + ((size_t)(q0 + r) << 6) + c];
        split_store(qHi, qLo, r, c, v);
    }

    const unsigned qH = (unsigned)__cvta_generic_to_shared(qHi);
    const unsigned qL = (unsigned)__cvta_generic_to_shared(qLo);
    const unsigned kH = (unsigned)__cvta_generic_to_shared(kHi);
    const unsigned kL = (unsigned)__cvta_generic_to_shared(kLo);

    // ---- phase 1: 256-wide k tiles, 16 warps = 2(m16) x 8(n32) ----
    const int wm1 = (warp & 1) << 4;
    const int wn1 = (warp >> 1) << 5;
    const int ntile1 = (q0 + 32 + 255) >> 8;

    for (int kt = 0; kt < ntile1; kt++) {
        const int k0 = kt << 8;
        __syncthreads();
        #pragma unroll
        for (int i = 0; i < 4; i++) {
            int f = tid + (i << 9); int row = f >> 6, kc = (f & 63) << 2;
            *(float4*)&strip[row * STRIP + k0 + kc] =
                *(const float4*)&attn[((size_t)b << 20) + ((size_t)(q0 + row) << 10) + k0 + kc];
        }
        #pragma unroll
        for (int i = 0; i < 8; i++) {
            int f = tid + (i << 9); int r = f >> 4, c = (f & 15) << 2;
            float4 v = *(const float4*)&K[((size_t)b << 16) + ((size_t)(k0 + r) << 6) + c];
            split_store(kHi, kLo, r, c, v);
        }
        __syncthreads();

        float c_[4][4] = {};
        const int arow = wm1 + (lane & 15);
        #pragma unroll
        for (int ks = 0; ks < 4; ks++) {
            const int cb = (ks << 1) + lhi;
            unsigned a_hi[4], a_lo[4];
            ldsm4(a_hi, qH + sw_off(arow, cb));
            ldsm4(a_lo, qL + sw_off(arow, cb));
            unsigned b_hi[2][4], b_lo[2][4];
            #pragma unroll
            for (int h = 0; h < 2; h++) {
                int brow = wn1 + (h << 4) + (lane & 15);
                ldsm4(b_hi[h], kH + sw_off(brow, cb));
                ldsm4(b_lo[h], kL + sw_off(brow, cb));
            }
            #pragma unroll
            for (int j = 0; j < 4; j++) {
                const int h = j >> 1, o = j & 1;
                unsigned bh[2] = {b_hi[h][o], b_hi[h][o + 2]};
                unsigned bl[2] = {b_lo[h][o], b_lo[h][o + 2]};
                mma_bf16(c_[j], a_hi, bh);
                mma_bf16(c_[j], a_hi, bl);
                mma_bf16(c_[j], a_lo, bh);
            }
        }
        const int row0 = wm1 + (lane >> 2);
        const int coll = (lane & 3) << 1;
        #pragma unroll
        for (int j = 0; j < 4; j++) {
            int colk = k0 + wn1 + (j << 3) + coll;
            {
                int qr = q0 + row0;
                float2 bs = *(float2*)&strip[row0 * STRIP + colk];
                float s0 = (colk     <= qr) ? fmaf(c_[j][0], 0.125f, bs.x) : 0.f;
                float s1 = (colk + 1 <= qr) ? fmaf(c_[j][1], 0.125f, bs.y) : 0.f;
                *(float2*)&strip[row0 * STRIP + colk] = make_float2(s0, s1);
            }
            {
                int qr = q0 + row0 + 8;
                float2 bs = *(float2*)&strip[(row0 + 8) * STRIP + colk];
                float s0 = (colk     <= qr) ? fmaf(c_[j][2], 0.125f, bs.x) : 0.f;
                float s1 = (colk + 1 <= qr) ? fmaf(c_[j][3], 0.125f, bs.y) : 0.f;
                *(float2*)&strip[(row0 + 8) * STRIP + colk] = make_float2(s0, s1);
            }
        }
    }
    __syncthreads();

    // ---- phase 2: softmax per row (FFMA-pipe exp) ----
    {
        const int w = warp;
        #pragma unroll
        for (int r = 0; r < 2; r++) {
            int row = (w << 1) + r;
            int qr  = q0 + row;
            float m = -1e30f;
            for (int kk = lane; kk <= qr; kk += 32)
                m = fmaxf(m, strip[row * STRIP + kk]);
            #pragma unroll
            for (int o = 16; o; o >>= 1)
                m = fmaxf(m, __shfl_xor_sync(0xffffffffu, m, o));
            float ssum = 0.f;
            for (int kk = lane; kk <= qr; kk += 32) {
                float e = fast_exp(strip[row * STRIP + kk] - m);
                strip[row * STRIP + kk] = e;
                ssum += e;
            }
            #pragma unroll
            for (int o = 16; o; o >>= 1)
                ssum += __shfl_xor_sync(0xffffffffu, ssum, o);
            if (lane == 0) sInv[row] = 1.0f / ssum;
        }
    }
    __syncthreads();

    // ---- phase 3: write normalized attn ----
    #pragma unroll
    for (int i = 0; i < 16; i++) {
        int f = tid + (i << 9);
        int row = f >> 8;
        int kc  = (f & 255) << 2;
        int qr  = q0 + row;
        float inv = sInv[row];
        float4 e = *(const float4*)&strip[row * STRIP + kc];
        float4 o;
        o.x = (kc     <= qr) ? e.x * inv : 0.f;
        o.y = (kc + 1 <= qr) ? e.y * inv : 0.f;
        o.z = (kc + 2 <= qr) ? e.z * inv : 0.f;
        o.w = (kc + 3 <= qr) ? e.w * inv : 0.f;
        *(float4*)&attn[((size_t)b << 20) + ((size_t)qr << 10) + kc] = o;
    }

    // ---- phase 4: out = P @ V.  128-wide k tiles, 16 warps = 2m x 2n x 4kg ----
    const int wm4 = (warp & 1) << 4;
    const int wn4 = ((warp >> 1) & 1) << 5;
    const int kg  = warp >> 2;
    const int ntile4 = (q0 + 32 + 127) >> 7;
    const unsigned pH = (unsigned)__cvta_generic_to_shared(pHi);
    const unsigned pL = (unsigned)__cvta_generic_to_shared(pLo);
    const unsigned vH = (unsigned)__cvta_generic_to_shared(vHi);
    const unsigned vL = (unsigned)__cvta_generic_to_shared(vLo);

    float c4[4][4] = {};

    for (int kt = 0; kt < ntile4; kt++) {
        const int k0 = kt << 7;
        __syncthreads();
        #pragma unroll
        for (int i = 0; i < 2; i++) {
            int f = tid + (i << 9); int r = f >> 5, c = (f & 31) << 2;
            float4 v = *(const float4*)&strip[r * STRIP + k0 + c];
            int kh = c >> 6;
            split_store(pHi + (kh << 11), pLo + (kh << 11), r, c & 63, v);
        }
        #pragma unroll
        for (int i = 0; i < 4; i++) {
            int f = tid + (i << 9); int r = f >> 4, c = (f & 15) << 2;
            float4 v = *(const float4*)&V[((size_t)b << 16) + ((size_t)(k0 + r) << 6) + c];
            split_store(vHi, vLo, r, c, v);
        }
        __syncthreads();

        const int arow = wm4 + (lane & 15);
        #pragma unroll
        for (int ks = 0; ks < 2; ks++) {
            const int ko = (kg << 5) + (ks << 4);
            const int kh = ko >> 6;
            const int cbb = (ko & 63) >> 3;
            unsigned a_hi[4], a_lo[4];
            ldsm4(a_hi, pH + (kh << 12) + sw_off(arow, cbb + lhi));
            ldsm4(a_lo, pL + (kh << 12) + sw_off(arow, cbb + lhi));
            unsigned b_hi[2][4], b_lo[2][4];
            const int brow = ko + (lane & 15);
            #pragma unroll
            for (int h = 0; h < 2; h++) {
                int bcb = ((wn4 + (h << 4)) >> 3) + lhi;
                ldsm4t(b_hi[h], vH + sw_off(brow, bcb));
                ldsm4t(b_lo[h], vL + sw_off(brow, bcb));
            }
            #pragma unroll
            for (int j = 0; j < 4; j++) {
                const int h = j >> 1, o = j & 1;
                unsigned bh[2] = {b_hi[h][o << 1], b_hi[h][(o << 1) + 1]};
                unsigned bl[2] = {b_lo[h][o << 1], b_lo[h][(o << 1) + 1]};
                mma_bf16(c4[j], a_hi, bh);
                mma_bf16(c4[j], a_hi, bl);
                mma_bf16(c4[j], a_lo, bh);
            }
        }
    }
    __syncthreads();

    const int row0 = wm4 + (lane >> 2);
    const int coll = (lane & 3) << 1;
    if (kg > 0) {
        #pragma unroll
        for (int j = 0; j < 4; j++) {
            int col = wn4 + (j << 3) + coll;
            *(float2*)&red[((kg - 1) << 11) + (row0 << 6) + col] =
                make_float2(c4[j][0], c4[j][1]);
            *(float2*)&red[((kg - 1) << 11) + ((row0 + 8) << 6) + col] =
                make_float2(c4[j][2], c4[j][3]);
        }
    }
    __syncthreads();
    if (kg == 0) {
        const float inv0 = sInv[row0];
        const float inv1 = sInv[row0 + 8];
        #pragma unroll
        for (int j = 0; j < 4; j++) {
            int col = wn4 + (j << 3) + coll;
            float2 s0 = make_float2(c4[j][0], c4[j][1]);
            float2 s1 = make_float2(c4[j][2], c4[j][3]);
            #pragma unroll
            for (int g = 0; g < 3; g++) {
                float2 p0 = *(const float2*)&red[(g << 11) + (row0 << 6) + col];
                float2 p1 = *(const float2*)&red[(g << 11) + ((row0 + 8) << 6) + col];
                s0.x += p0.x; s0.y += p0.y;
                s1.x += p1.x; s1.y += p1.y;
            }
            *(float2*)&out[((size_t)b << 16) + ((size_t)(q0 + row0) << 6) + col] =
                make_float2(s0.x * inv0, s0.y * inv0);
            *(float2*)&out[((size_t)b << 16) + ((size_t)(q0 + row0 + 8) << 6) + col] =
                make_float2(s1.x * inv1, s1.y * inv1);
        }
    }
}

// ---------------------------------------------------------------------------
// Kernel 3: out[b,q,d] += sum_k attn[b,q,k] * R_v[q,k,d]   (unchanged)
// ---------------------------------------------------------------------------
__global__ void __launch_bounds__(256) k_rv(const float* __restrict__ attn,
                                            const float* __restrict__ Rv,
                                            float* __restrict__ out)
{
    const int q   = 1023 - blockIdx.x;
    const int tid = threadIdx.x;
    const int ntile = (q >> 6) + 1;

    __shared__ __align__(16) __nv_bfloat16 aHi[4096], aLo[4096], bHi[4096], bLo[4096];

    const int warp = tid >> 5, lane = tid & 31;
    const int wm = (warp & 3) << 4;
    const int wn = (warp >> 2) << 5;

    const unsigned aH = (unsigned)__cvta_generic_to_shared(aHi);
    const unsigned aL = (unsigned)__cvta_generic_to_shared(aLo);
    const unsigned bH = (unsigned)__cvta_generic_to_shared(bHi);
    const unsigned bL = (unsigned)__cvta_generic_to_shared(bLo);

    const int arow = wm + (lane & 15);
    const int lhi  = lane >> 4;

    float c_[4][4] = {};

    for (int kt = 0; kt < ntile; kt++) {
        const int k0 = kt << 6;
        __syncthreads();
        #pragma unroll
        for (int i = 0; i < 4; i++) {
            int f = tid + (i << 8); int r = f >> 4, c = (f & 15) << 2;
            float4 v = *(const float4*)&attn[((size_t)r << 20) + ((size_t)q << 10) + (size_t)(k0 + c)];
            split_store(aHi, aLo, r, c, v);
        }
        #pragma unroll
        for (int i = 0; i < 4; i++) {
            int f = tid + (i << 8); int r = f >> 4, c = (f & 15) << 2;
            float4 v = *(const float4*)&Rv[(((size_t)q << 10) + (size_t)(k0 + r)) * 64 + c];
            split_store(bHi, bLo, r, c, v);
        }
        __syncthreads();

        #pragma unroll
        for (int ks = 0; ks < 4; ks++) {
            const int cb = (ks << 1) + lhi;
            unsigned a_hi[4], a_lo[4];
            ldsm4(a_hi, aH + sw_off(arow, cb));
            ldsm4(a_lo, aL + sw_off(arow, cb));
            unsigned b_hi[2][4], b_lo[2][4];
            #pragma unroll
            for (int h = 0; h < 2; h++) {
                int brow = (ks << 4) + (lane & 15);
                int bcb  = ((wn + (h << 4)) >> 3) + lhi;
                ldsm4t(b_hi[h], bH + sw_off(brow, bcb));
                ldsm4t(b_lo[h], bL + sw_off(brow, bcb));
            }
            #pragma unroll
            for (int j = 0; j < 4; j++) {
                const int h = j >> 1, o = j & 1;
                unsigned bh[2] = {b_hi[h][o << 1], b_hi[h][(o << 1) + 1]};
                unsigned bl[2] = {b_lo[h][o << 1], b_lo[h][(o << 1) + 1]};
                mma_bf16(c_[j], a_hi, bh);
                mma_bf16(c_[j], a_hi, bl);
                mma_bf16(c_[j], a_lo, bh);
            }
        }
    }

    const int row0 = wm + (lane >> 2);
    const int coll = (lane & 3) << 1;
    #pragma unroll
    for (int j = 0; j < 4; j++) {
        int col = wn + (j << 3) + coll;
        {
            float2* p = (float2*)&out[((size_t)row0 << 16) + ((size_t)q << 6) + col];
            float2 o = *p; o.x += c_[j][0]; o.y += c_[j][1]; *p = o;
        }
        {
            float2* p = (float2*)&out[((size_t)(row0 + 8) << 16) + ((size_t)q << 6) + col];
            float2 o = *p; o.x += c_[j][2]; o.y += c_[j][3]; *p = o;
        }
    }
}

// ---------------------------------------------------------------------------
extern "C" void kernel_launch(void* const* d_in, const int* in_sizes, int n_in,
                              void* d_out, int out_size)
{
    const float* Q  = (const float*)d_in[0];
    const float* K  = (const float*)d_in[1];
    const float* V  = (const float*)d_in[2];
    const float* Rk = (const float*)d_in[3];
    const float* Rv = (const float*)d_in[4];
    float* out  = (float*)d_out;
    float* attn = out + SZ_OUT;

    const int smem2 = 32 * STRIP * (int)sizeof(float) + 36864 * (int)sizeof(__nv_bfloat16);
    cudaFuncSetAttribute(k_attn, cudaFuncAttributeMaxDynamicSharedMemorySize, smem2);

    k_bias<<<dim3(16, 1024), 256>>>(Q, Rk, attn);
    k_attn<<<dim3(64, 32), 512, smem2>>>(Q, K, V, attn, out);
    k_rv<<<1024, 256>>>(attn, Rv, out);
}

// round 12
// speedup vs baseline: 1.0327x; 1.0327x over previous
#include <cuda_runtime.h>
#include <cuda_bf16.h>

#define SZ_OUT (64ull * 1024ull * 64ull)
#define STRIP 1028

// 128 MB bf16 bias scratch: [b][q][k] = b<<20 | q<<10 | k
__device__ __nv_bfloat16 g_bias[1ull << 26];

// ===========================================================================
// bf16 split-GEMM helpers (mma.sync m16n8k16, 3-MMA fp32 emulation)
// 64-col bf16 tiles; chunk cb (0..7) of row r stored at chunk (cb ^ (r & 7)).
// ===========================================================================
__device__ __forceinline__ unsigned pk_bf2(float a, float b) {
    __nv_bfloat162 t = __floats2bfloat162_rn(a, b);
    return *reinterpret_cast<unsigned*>(&t);
}
__device__ __forceinline__ float2 bf2f(unsigned u) {
    __nv_bfloat162 h = *reinterpret_cast<__nv_bfloat162*>(&u);
    return __bfloat1622float2(h);
}

__device__ __forceinline__ void split_store(__nv_bfloat16* hi, __nv_bfloat16* lo,
                                            int r, int c, float4 v)
{
    int cb  = c >> 3;
    int off = (r << 6) + ((cb ^ (r & 7)) << 3) + (c & 7);
    float hx = __bfloat162float(__float2bfloat16(v.x));
    float hy = __bfloat162float(__float2bfloat16(v.y));
    float hz = __bfloat162float(__float2bfloat16(v.z));
    float hw = __bfloat162float(__float2bfloat16(v.w));
    *(uint2*)(hi + off) = make_uint2(pk_bf2(hx, hy), pk_bf2(hz, hw));
    *(uint2*)(lo + off) = make_uint2(pk_bf2(v.x - hx, v.y - hy),
                                     pk_bf2(v.z - hz, v.w - hw));
}

__device__ __forceinline__ void ldsm4(unsigned* r, unsigned addr) {
    asm volatile("ldmatrix.sync.aligned.m8n8.x4.shared.b16 {%0,%1,%2,%3}, [%4];"
                 : "=r"(r[0]), "=r"(r[1]), "=r"(r[2]), "=r"(r[3]) : "r"(addr));
}
__device__ __forceinline__ void ldsm4t(unsigned* r, unsigned addr) {
    asm volatile("ldmatrix.sync.aligned.m8n8.x4.trans.shared.b16 {%0,%1,%2,%3}, [%4];"
                 : "=r"(r[0]), "=r"(r[1]), "=r"(r[2]), "=r"(r[3]) : "r"(addr));
}
__device__ __forceinline__ void mma_bf16(float* c, const unsigned* a, const unsigned* b) {
    asm volatile("mma.sync.aligned.m16n8k16.row.col.f32.bf16.bf16.f32 "
                 "{%0,%1,%2,%3}, {%4,%5,%6,%7}, {%8,%9}, {%0,%1,%2,%3};"
                 : "+f"(c[0]), "+f"(c[1]), "+f"(c[2]), "+f"(c[3])
                 : "r"(a[0]), "r"(a[1]), "r"(a[2]), "r"(a[3]), "r"(b[0]), "r"(b[1]));
}

__device__ __forceinline__ unsigned sw_off(int r, int cb) {
    return (unsigned)((r << 7) + (((cb ^ (r & 7))) << 4));
}

// FFMA-pipe exp for t <= 0
__device__ __forceinline__ float fast_exp(float t) {
    float y = t * 1.4426950408889634f;
    int   n = __float2int_rn(y);
    float f = y - (float)n;
    float p = 1.3333558146428443e-3f;
    p = fmaf(p, f, 9.6181291076284772e-3f);
    p = fmaf(p, f, 5.5504108664821580e-2f);
    p = fmaf(p, f, 2.4022650695910071e-1f);
    p = fmaf(p, f, 6.9314718055994531e-1f);
    p = fmaf(p, f, 1.0f);
    int e = n + 127;
    e = e < 0 ? 0 : e;
    return p * __int_as_float(e << 23);
}

// ---------------------------------------------------------------------------
// Kernel 1: g_bias[b,q,k] = bf16( 0.125 * sum_d Q[b,q,d] * R_k[q,k,d] )
// ---------------------------------------------------------------------------
__global__ void __launch_bounds__(256) k_bias(const float* __restrict__ Q,
                                              const float* __restrict__ Rk)
{
    const int q  = blockIdx.y;
    const int k0 = blockIdx.x << 6;
    if (k0 > q) return;

    __shared__ __align__(16) __nv_bfloat16 aHi[4096], aLo[4096], bHi[4096], bLo[4096];
    const int tid = threadIdx.x;

    #pragma unroll
    for (int i = 0; i < 4; i++) {
        int f = tid + (i << 8); int r = f >> 4, c = (f & 15) << 2;
        float4 v = *(const float4*)&Q[((size_t)r << 16) + ((size_t)q << 6) + c];
        split_store(aHi, aLo, r, c, v);
    }
    #pragma unroll
    for (int i = 0; i < 4; i++) {
        int f = tid + (i << 8); int r = f >> 4, c = (f & 15) << 2;
        float4 v = *(const float4*)&Rk[(((size_t)q << 10) + (size_t)(k0 + r)) * 64 + c];
        split_store(bHi, bLo, r, c, v);
    }
    __syncthreads();

    const int warp = tid >> 5, lane = tid & 31;
    const int wm = (warp & 3) << 4;
    const int wn = (warp >> 2) << 5;

    const unsigned aH = (unsigned)__cvta_generic_to_shared(aHi);
    const unsigned aL = (unsigned)__cvta_generic_to_shared(aLo);
    const unsigned bH = (unsigned)__cvta_generic_to_shared(bHi);
    const unsigned bL = (unsigned)__cvta_generic_to_shared(bLo);

    const int arow = wm + (lane & 15);
    const int lhi  = lane >> 4;

    float c_[4][4] = {};

    #pragma unroll
    for (int ks = 0; ks < 4; ks++) {
        const int cb = (ks << 1) + lhi;
        unsigned a_hi[4], a_lo[4];
        ldsm4(a_hi, aH + sw_off(arow, cb));
        ldsm4(a_lo, aL + sw_off(arow, cb));
        unsigned b_hi[2][4], b_lo[2][4];
        #pragma unroll
        for (int h = 0; h < 2; h++) {
            int brow = wn + (h << 4) + (lane & 15);
            ldsm4(b_hi[h], bH + sw_off(brow, cb));
            ldsm4(b_lo[h], bL + sw_off(brow, cb));
        }
        #pragma unroll
        for (int j = 0; j < 4; j++) {
            const int h = j >> 1, o = j & 1;
            unsigned bh[2] = {b_hi[h][o], b_hi[h][o + 2]};
            unsigned bl[2] = {b_lo[h][o], b_lo[h][o + 2]};
            mma_bf16(c_[j], a_hi, bh);
            mma_bf16(c_[j], a_hi, bl);
            mma_bf16(c_[j], a_lo, bh);
        }
    }

    const int row0 = wm + (lane >> 2);
    const int coll = (lane & 3) << 1;
    #pragma unroll
    for (int j = 0; j < 4; j++) {
        int col = k0 + wn + (j << 3) + coll;
        *(unsigned*)&g_bias[((size_t)row0 << 20) + ((size_t)q << 10) + col] =
            pk_bf2(c_[j][0] * 0.125f, c_[j][1] * 0.125f);
        *(unsigned*)&g_bias[((size_t)(row0 + 8) << 20) + ((size_t)q << 10) + col] =
            pk_bf2(c_[j][2] * 0.125f, c_[j][3] * 0.125f);
    }
}

// ---------------------------------------------------------------------------
// Kernel 2: per (b, 32-row q strip). 512 threads, ~200 KB smem.
// ---------------------------------------------------------------------------
__global__ void __launch_bounds__(512) k_attn(const float* __restrict__ Q,
                                              const float* __restrict__ K,
                                              const float* __restrict__ V,
                                              float* attn,
                                              float* __restrict__ out)
{
    extern __shared__ float sm[];
    float* strip = sm;                                      // [32][1028]
    __nv_bfloat16* bufs = (__nv_bfloat16*)(strip + 32 * STRIP);
    __nv_bfloat16* qHi = bufs;
    __nv_bfloat16* qLo = bufs + 2048;
    __nv_bfloat16* kHi = bufs + 4096;
    __nv_bfloat16* kLo = bufs + 20480;
    __nv_bfloat16* pHi = bufs;
    __nv_bfloat16* pLo = bufs + 4096;
    __nv_bfloat16* vHi = bufs + 8192;
    __nv_bfloat16* vLo = bufs + 16384;
    float* red = (float*)bufs;
    __shared__ float sInv[32];

    const int b   = blockIdx.x;
    const int q0  = (gridDim.y - 1 - blockIdx.y) << 5;
    const int tid = threadIdx.x;
    const int warp = tid >> 5, lane = tid & 31, lhi = lane >> 4;

    {
        int r = tid >> 4, c = (tid & 15) << 2;
        float4 v = *(const float4*)&Q[((size_t)b << 16) + ((size_t)(q0 + r) << 6) + c];
        split_store(qHi, qLo, r, c, v);
    }

    const unsigned qH = (unsigned)__cvta_generic_to_shared(qHi);
    const unsigned qL = (unsigned)__cvta_generic_to_shared(qLo);
    const unsigned kH = (unsigned)__cvta_generic_to_shared(kHi);
    const unsigned kL = (unsigned)__cvta_generic_to_shared(kLo);

    // ---- phase 1: 256-wide k tiles, 16 warps = 2(m16) x 8(n32) ----
    const int wm1 = (warp & 1) << 4;
    const int wn1 = (warp >> 1) << 5;
    const int ntile1 = (q0 + 32 + 255) >> 8;

    for (int kt = 0; kt < ntile1; kt++) {
        const int k0 = kt << 8;
        __syncthreads();
        #pragma unroll
        for (int i = 0; i < 8; i++) {
            int f = tid + (i << 9); int r = f >> 4, c = (f & 15) << 2;
            float4 v = *(const float4*)&K[((size_t)b << 16) + ((size_t)(k0 + r) << 6) + c];
            split_store(kHi, kLo, r, c, v);
        }
        __syncthreads();

        float c_[4][4] = {};
        const int arow = wm1 + (lane & 15);
        #pragma unroll
        for (int ks = 0; ks < 4; ks++) {
            const int cb = (ks << 1) + lhi;
            unsigned a_hi[4], a_lo[4];
            ldsm4(a_hi, qH + sw_off(arow, cb));
            ldsm4(a_lo, qL + sw_off(arow, cb));
            unsigned b_hi[2][4], b_lo[2][4];
            #pragma unroll
            for (int h = 0; h < 2; h++) {
                int brow = wn1 + (h << 4) + (lane & 15);
                ldsm4(b_hi[h], kH + sw_off(brow, cb));
                ldsm4(b_lo[h], kL + sw_off(brow, cb));
            }
            #pragma unroll
            for (int j = 0; j < 4; j++) {
                const int h = j >> 1, o = j & 1;
                unsigned bh[2] = {b_hi[h][o], b_hi[h][o + 2]};
                unsigned bl[2] = {b_lo[h][o], b_lo[h][o + 2]};
                mma_bf16(c_[j], a_hi, bh);
                mma_bf16(c_[j], a_hi, bl);
                mma_bf16(c_[j], a_lo, bh);
            }
        }
        // epilogue: scores = qk*0.125 + bias(bf16, pre-scaled), mask -> strip
        const int row0 = wm1 + (lane >> 2);
        const int coll = (lane & 3) << 1;
        #pragma unroll
        for (int j = 0; j < 4; j++) {
            int colk = k0 + wn1 + (j << 3) + coll;
            {
                int qr = q0 + row0;
                float2 bs = bf2f(*(const unsigned*)&g_bias[((size_t)b << 20) + ((size_t)qr << 10) + colk]);
                float s0 = (colk     <= qr) ? fmaf(c_[j][0], 0.125f, bs.x) : 0.f;
                float s1 = (colk + 1 <= qr) ? fmaf(c_[j][1], 0.125f, bs.y) : 0.f;
                *(float2*)&strip[row0 * STRIP + colk] = make_float2(s0, s1);
            }
            {
                int qr = q0 + row0 + 8;
                float2 bs = bf2f(*(const unsigned*)&g_bias[((size_t)b << 20) + ((size_t)qr << 10) + colk]);
                float s0 = (colk     <= qr) ? fmaf(c_[j][2], 0.125f, bs.x) : 0.f;
                float s1 = (colk + 1 <= qr) ? fmaf(c_[j][3], 0.125f, bs.y) : 0.f;
                *(float2*)&strip[(row0 + 8) * STRIP + colk] = make_float2(s0, s1);
            }
        }
    }
    __syncthreads();

    // ---- phase 2: softmax per row ----
    {
        const int w = warp;
        #pragma unroll
        for (int r = 0; r < 2; r++) {
            int row = (w << 1) + r;
            int qr  = q0 + row;
            float m = -1e30f;
            for (int kk = lane; kk <= qr; kk += 32)
                m = fmaxf(m, strip[row * STRIP + kk]);
            #pragma unroll
            for (int o = 16; o; o >>= 1)
                m = fmaxf(m, __shfl_xor_sync(0xffffffffu, m, o));
            float ssum = 0.f;
            for (int kk = lane; kk <= qr; kk += 32) {
                float e = fast_exp(strip[row * STRIP + kk] - m);
                strip[row * STRIP + kk] = e;
                ssum += e;
            }
            #pragma unroll
            for (int o = 16; o; o >>= 1)
                ssum += __shfl_xor_sync(0xffffffffu, ssum, o);
            if (lane == 0) sInv[row] = 1.0f / ssum;
        }
    }
    __syncthreads();

    // ---- phase 3: write normalized attn ----
    #pragma unroll
    for (int i = 0; i < 16; i++) {
        int f = tid + (i << 9);
        int row = f >> 8;
        int kc  = (f & 255) << 2;
        int qr  = q0 + row;
        float inv = sInv[row];
        float4 e = *(const float4*)&strip[row * STRIP + kc];
        float4 o;
        o.x = (kc     <= qr) ? e.x * inv : 0.f;
        o.y = (kc + 1 <= qr) ? e.y * inv : 0.f;
        o.z = (kc + 2 <= qr) ? e.z * inv : 0.f;
        o.w = (kc + 3 <= qr) ? e.w * inv : 0.f;
        *(float4*)&attn[((size_t)b << 20) + ((size_t)qr << 10) + kc] = o;
    }

    // ---- phase 4: out = P @ V.  128-wide k tiles, 16 warps = 2m x 2n x 4kg ----
    const int wm4 = (warp & 1) << 4;
    const int wn4 = ((warp >> 1) & 1) << 5;
    const int kg  = warp >> 2;
    const int ntile4 = (q0 + 32 + 127) >> 7;
    const unsigned pH = (unsigned)__cvta_generic_to_shared(pHi);
    const unsigned pL = (unsigned)__cvta_generic_to_shared(pLo);
    const unsigned vH = (unsigned)__cvta_generic_to_shared(vHi);
    const unsigned vL = (unsigned)__cvta_generic_to_shared(vLo);

    float c4[4][4] = {};

    for (int kt = 0; kt < ntile4; kt++) {
        const int k0 = kt << 7;
        __syncthreads();
        #pragma unroll
        for (int i = 0; i < 2; i++) {
            int f = tid + (i << 9); int r = f >> 5, c = (f & 31) << 2;
            float4 v = *(const float4*)&strip[r * STRIP + k0 + c];
            int kh = c >> 6;
            split_store(pHi + (kh << 11), pLo + (kh << 11), r, c & 63, v);
        }
        #pragma unroll
        for (int i = 0; i < 4; i++) {
            int f = tid + (i << 9); int r = f >> 4, c = (f & 15) << 2;
            float4 v = *(const float4*)&V[((size_t)b << 16) + ((size_t)(k0 + r) << 6) + c];
            split_store(vHi, vLo, r, c, v);
        }
        __syncthreads();

        const int arow = wm4 + (lane & 15);
        #pragma unroll
        for (int ks = 0; ks < 2; ks++) {
            const int ko = (kg << 5) + (ks << 4);
            const int kh = ko >> 6;
            const int cbb = (ko & 63) >> 3;
            unsigned a_hi[4], a_lo[4];
            ldsm4(a_hi, pH + (kh << 12) + sw_off(arow, cbb + lhi));
            ldsm4(a_lo, pL + (kh << 12) + sw_off(arow, cbb + lhi));
            unsigned b_hi[2][4], b_lo[2][4];
            const int brow = ko + (lane & 15);
            #pragma unroll
            for (int h = 0; h < 2; h++) {
                int bcb = ((wn4 + (h << 4)) >> 3) + lhi;
                ldsm4t(b_hi[h], vH + sw_off(brow, bcb));
                ldsm4t(b_lo[h], vL + sw_off(brow, bcb));
            }
            #pragma unroll
            for (int j = 0; j < 4; j++) {
                const int h = j >> 1, o = j & 1;
                unsigned bh[2] = {b_hi[h][o << 1], b_hi[h][(o << 1) + 1]};
                unsigned bl[2] = {b_lo[h][o << 1], b_lo[h][(o << 1) + 1]};
                mma_bf16(c4[j], a_hi, bh);
                mma_bf16(c4[j], a_hi, bl);
                mma_bf16(c4[j], a_lo, bh);
            }
        }
    }
    __syncthreads();

    const int row0 = wm4 + (lane >> 2);
    const int coll = (lane & 3) << 1;
    if (kg > 0) {
        #pragma unroll
        for (int j = 0; j < 4; j++) {
            int col = wn4 + (j << 3) + coll;
            *(float2*)&red[((kg - 1) << 11) + (row0 << 6) + col] =
                make_float2(c4[j][0], c4[j][1]);
            *(float2*)&red[((kg - 1) << 11) + ((row0 + 8) << 6) + col] =
                make_float2(c4[j][2], c4[j][3]);
        }
    }
    __syncthreads();
    if (kg == 0) {
        const float inv0 = sInv[row0];
        const float inv1 = sInv[row0 + 8];
        #pragma unroll
        for (int j = 0; j < 4; j++) {
            int col = wn4 + (j << 3) + coll;
            float2 s0 = make_float2(c4[j][0], c4[j][1]);
            float2 s1 = make_float2(c4[j][2], c4[j][3]);
            #pragma unroll
            for (int g = 0; g < 3; g++) {
                float2 p0 = *(const float2*)&red[(g << 11) + (row0 << 6) + col];
                float2 p1 = *(const float2*)&red[(g << 11) + ((row0 + 8) << 6) + col];
                s0.x += p0.x; s0.y += p0.y;
                s1.x += p1.x; s1.y += p1.y;
            }
            *(float2*)&out[((size_t)b << 16) + ((size_t)(q0 + row0) << 6) + col] =
                make_float2(s0.x * inv0, s0.y * inv0);
            *(float2*)&out[((size_t)b << 16) + ((size_t)(q0 + row0 + 8) << 6) + col] =
                make_float2(s1.x * inv1, s1.y * inv1);
        }
    }
}

// ---------------------------------------------------------------------------
// Kernel 3: out[b,q,d] += sum_k attn[b,q,k] * R_v[q,k,d]   (unchanged)
// ---------------------------------------------------------------------------
__global__ void __launch_bounds__(256) k_rv(const float* __restrict__ attn,
                                            const float* __restrict__ Rv,
                                            float* __restrict__ out)
{
    const int q   = 1023 - blockIdx.x;
    const int tid = threadIdx.x;
    const int ntile = (q >> 6) + 1;

    __shared__ __align__(16) __nv_bfloat16 aHi[4096], aLo[4096], bHi[4096], bLo[4096];

    const int warp = tid >> 5, lane = tid & 31;
    const int wm = (warp & 3) << 4;
    const int wn = (warp >> 2) << 5;

    const unsigned aH = (unsigned)__cvta_generic_to_shared(aHi);
    const unsigned aL = (unsigned)__cvta_generic_to_shared(aLo);
    const unsigned bH = (unsigned)__cvta_generic_to_shared(bHi);
    const unsigned bL = (unsigned)__cvta_generic_to_shared(bLo);

    const int arow = wm + (lane & 15);
    const int lhi  = lane >> 4;

    float c_[4][4] = {};

    for (int kt = 0; kt < ntile; kt++) {
        const int k0 = kt << 6;
        __syncthreads();
        #pragma unroll
        for (int i = 0; i < 4; i++) {
            int f = tid + (i << 8); int r = f >> 4, c = (f & 15) << 2;
            float4 v = *(const float4*)&attn[((size_t)r << 20) + ((size_t)q << 10) + (size_t)(k0 + c)];
            split_store(aHi, aLo, r, c, v);
        }
        #pragma unroll
        for (int i = 0; i < 4; i++) {
            int f = tid + (i << 8); int r = f >> 4, c = (f & 15) << 2;
            float4 v = *(const float4*)&Rv[(((size_t)q << 10) + (size_t)(k0 + r)) * 64 + c];
            split_store(bHi, bLo, r, c, v);
        }
        __syncthreads();

        #pragma unroll
        for (int ks = 0; ks < 4; ks++) {
            const int cb = (ks << 1) + lhi;
            unsigned a_hi[4], a_lo[4];
            ldsm4(a_hi, aH + sw_off(arow, cb));
            ldsm4(a_lo, aL + sw_off(arow, cb));
            unsigned b_hi[2][4], b_lo[2][4];
            #pragma unroll
            for (int h = 0; h < 2; h++) {
                int brow = (ks << 4) + (lane & 15);
                int bcb  = ((wn + (h << 4)) >> 3) + lhi;
                ldsm4t(b_hi[h], bH + sw_off(brow, bcb));
                ldsm4t(b_lo[h], bL + sw_off(brow, bcb));
            }
            #pragma unroll
            for (int j = 0; j < 4; j++) {
                const int h = j >> 1, o = j & 1;
                unsigned bh[2] = {b_hi[h][o << 1], b_hi[h][(o << 1) + 1]};
                unsigned bl[2] = {b_lo[h][o << 1], b_lo[h][(o << 1) + 1]};
                mma_bf16(c_[j], a_hi, bh);
                mma_bf16(c_[j], a_hi, bl);
                mma_bf16(c_[j], a_lo, bh);
            }
        }
    }

    const int row0 = wm + (lane >> 2);
    const int coll = (lane & 3) << 1;
    #pragma unroll
    for (int j = 0; j < 4; j++) {
        int col = wn + (j << 3) + coll;
        {
            float2* p = (float2*)&out[((size_t)row0 << 16) + ((size_t)q << 6) + col];
            float2 o = *p; o.x += c_[j][0]; o.y += c_[j][1]; *p = o;
        }
        {
            float2* p = (float2*)&out[((size_t)(row0 + 8) << 16) + ((size_t)q << 6) + col];
            float2 o = *p; o.x += c_[j][2]; o.y += c_[j][3]; *p = o;
        }
    }
}

// ---------------------------------------------------------------------------
extern "C" void kernel_launch(void* const* d_in, const int* in_sizes, int n_in,
                              void* d_out, int out_size)
{
    const float* Q  = (const float*)d_in[0];
    const float* K  = (const float*)d_in[1];
    const float* V  = (const float*)d_in[2];
    const float* Rk = (const float*)d_in[3];
    const float* Rv = (const float*)d_in[4];
    float* out  = (float*)d_out;
    float* attn = out + SZ_OUT;

    const int smem2 = 32 * STRIP * (int)sizeof(float) + 36864 * (int)sizeof(__nv_bfloat16);
    cudaFuncSetAttribute(k_attn, cudaFuncAttributeMaxDynamicSharedMemorySize, smem2);

    k_bias<<<dim3(16, 1024), 256>>>(Q, Rk);
    k_attn<<<dim3(64, 32), 512, smem2>>>(Q, K, V, attn, out);
    k_rv<<<1024, 256>>>(attn, Rv, out);
}

// round 13
// speedup vs baseline: 1.0673x; 1.0335x over previous
#include <cuda_runtime.h>
#include <cuda_bf16.h>

#define SZ_OUT (64ull * 1024ull * 64ull)
#define STRIP 1028

// bf16 bias scratch: [b][q][k]
__device__ __align__(16) __nv_bfloat16 g_bias[1ull << 26];
// pre-split K/V in swizzled tile layout: idx = b<<16 | row<<6 | swizzled-col
__device__ __align__(16) __nv_bfloat16 g_Khi[1ull << 22], g_Klo[1ull << 22];
__device__ __align__(16) __nv_bfloat16 g_Vhi[1ull << 22], g_Vlo[1ull << 22];

// ===========================================================================
// bf16 split-GEMM helpers (mma.sync m16n8k16, 3-MMA fp32 emulation)
// ===========================================================================
__device__ __forceinline__ unsigned pk_bf2(float a, float b) {
    __nv_bfloat162 t = __floats2bfloat162_rn(a, b);
    return *reinterpret_cast<unsigned*>(&t);
}
__device__ __forceinline__ float2 bf2f(unsigned u) {
    __nv_bfloat162 h = *reinterpret_cast<__nv_bfloat162*>(&u);
    return __bfloat1622float2(h);
}

__device__ __forceinline__ void split_store(__nv_bfloat16* hi, __nv_bfloat16* lo,
                                            int r, int c, float4 v)
{
    int cb  = c >> 3;
    int off = (r << 6) + ((cb ^ (r & 7)) << 3) + (c & 7);
    float hx = __bfloat162float(__float2bfloat16(v.x));
    float hy = __bfloat162float(__float2bfloat16(v.y));
    float hz = __bfloat162float(__float2bfloat16(v.z));
    float hw = __bfloat162float(__float2bfloat16(v.w));
    *(uint2*)(hi + off) = make_uint2(pk_bf2(hx, hy), pk_bf2(hz, hw));
    *(uint2*)(lo + off) = make_uint2(pk_bf2(v.x - hx, v.y - hy),
                                     pk_bf2(v.z - hz, v.w - hw));
}

__device__ __forceinline__ void ldsm4(unsigned* r, unsigned addr) {
    asm volatile("ldmatrix.sync.aligned.m8n8.x4.shared.b16 {%0,%1,%2,%3}, [%4];"
                 : "=r"(r[0]), "=r"(r[1]), "=r"(r[2]), "=r"(r[3]) : "r"(addr));
}
__device__ __forceinline__ void ldsm4t(unsigned* r, unsigned addr) {
    asm volatile("ldmatrix.sync.aligned.m8n8.x4.trans.shared.b16 {%0,%1,%2,%3}, [%4];"
                 : "=r"(r[0]), "=r"(r[1]), "=r"(r[2]), "=r"(r[3]) : "r"(addr));
}
__device__ __forceinline__ void mma_bf16(float* c, const unsigned* a, const unsigned* b) {
    asm volatile("mma.sync.aligned.m16n8k16.row.col.f32.bf16.bf16.f32 "
                 "{%0,%1,%2,%3}, {%4,%5,%6,%7}, {%8,%9}, {%0,%1,%2,%3};"
                 : "+f"(c[0]), "+f"(c[1]), "+f"(c[2]), "+f"(c[3])
                 : "r"(a[0]), "r"(a[1]), "r"(a[2]), "r"(a[3]), "r"(b[0]), "r"(b[1]));
}

__device__ __forceinline__ unsigned sw_off(int r, int cb) {
    return (unsigned)((r << 7) + (((cb ^ (r & 7))) << 4));
}

// FFMA-pipe exp for t <= 0
__device__ __forceinline__ float fast_exp(float t) {
    float y = t * 1.4426950408889634f;
    int   n = __float2int_rn(y);
    float f = y - (float)n;
    float p = 1.3333558146428443e-3f;
    p = fmaf(p, f, 9.6181291076284772e-3f);
    p = fmaf(p, f, 5.5504108664821580e-2f);
    p = fmaf(p, f, 2.4022650695910071e-1f);
    p = fmaf(p, f, 6.9314718055994531e-1f);
    p = fmaf(p, f, 1.0f);
    int e = n + 127;
    e = e < 0 ? 0 : e;
    return p * __int_as_float(e << 23);
}

// ---------------------------------------------------------------------------
// Kernel 0: pre-split K and V to swizzled bf16 hi/lo. Grid (64 b, 8 rowblocks).
// ---------------------------------------------------------------------------
__global__ void __launch_bounds__(256) k_prep(const float* __restrict__ K,
                                              const float* __restrict__ V)
{
    const int b  = blockIdx.x;
    const int r0 = blockIdx.y << 7;
    const int tid = threadIdx.x;
    __nv_bfloat16* kh = g_Khi + ((size_t)b << 16);
    __nv_bfloat16* kl = g_Klo + ((size_t)b << 16);
    __nv_bfloat16* vh = g_Vhi + ((size_t)b << 16);
    __nv_bfloat16* vl = g_Vlo + ((size_t)b << 16);
    #pragma unroll
    for (int i = 0; i < 8; i++) {
        int f = tid + (i << 8);
        int r = r0 + (f >> 4), c = (f & 15) << 2;
        float4 kv = *(const float4*)&K[((size_t)b << 16) + ((size_t)r << 6) + c];
        float4 vv = *(const float4*)&V[((size_t)b << 16) + ((size_t)r << 6) + c];
        split_store(kh, kl, r, c, kv);
        split_store(vh, vl, r, c, vv);
    }
}

// ---------------------------------------------------------------------------
// Kernel 1: g_bias[b,q,k] = bf16( 0.125 * sum_d Q[b,q,d] * R_k[q,k,d] )
// ---------------------------------------------------------------------------
__global__ void __launch_bounds__(256) k_bias(const float* __restrict__ Q,
                                              const float* __restrict__ Rk)
{
    const int q  = blockIdx.y;
    const int k0 = blockIdx.x << 6;
    if (k0 > q) return;

    __shared__ __align__(16) __nv_bfloat16 aHi[4096], aLo[4096], bHi[4096], bLo[4096];
    const int tid = threadIdx.x;

    #pragma unroll
    for (int i = 0; i < 4; i++) {
        int f = tid + (i << 8); int r = f >> 4, c = (f & 15) << 2;
        float4 v = *(const float4*)&Q[((size_t)r << 16) + ((size_t)q << 6) + c];
        split_store(aHi, aLo, r, c, v);
    }
    #pragma unroll
    for (int i = 0; i < 4; i++) {
        int f = tid + (i << 8); int r = f >> 4, c = (f & 15) << 2;
        float4 v = *(const float4*)&Rk[(((size_t)q << 10) + (size_t)(k0 + r)) * 64 + c];
        split_store(bHi, bLo, r, c, v);
    }
    __syncthreads();

    const int warp = tid >> 5, lane = tid & 31;
    const int wm = (warp & 3) << 4;
    const int wn = (warp >> 2) << 5;

    const unsigned aH = (unsigned)__cvta_generic_to_shared(aHi);
    const unsigned aL = (unsigned)__cvta_generic_to_shared(aLo);
    const unsigned bH = (unsigned)__cvta_generic_to_shared(bHi);
    const unsigned bL = (unsigned)__cvta_generic_to_shared(bLo);

    const int arow = wm + (lane & 15);
    const int lhi  = lane >> 4;

    float c_[4][4] = {};

    #pragma unroll
    for (int ks = 0; ks < 4; ks++) {
        const int cb = (ks << 1) + lhi;
        unsigned a_hi[4], a_lo[4];
        ldsm4(a_hi, aH + sw_off(arow, cb));
        ldsm4(a_lo, aL + sw_off(arow, cb));
        unsigned b_hi[2][4], b_lo[2][4];
        #pragma unroll
        for (int h = 0; h < 2; h++) {
            int brow = wn + (h << 4) + (lane & 15);
            ldsm4(b_hi[h], bH + sw_off(brow, cb));
            ldsm4(b_lo[h], bL + sw_off(brow, cb));
        }
        #pragma unroll
        for (int j = 0; j < 4; j++) {
            const int h = j >> 1, o = j & 1;
            unsigned bh[2] = {b_hi[h][o], b_hi[h][o + 2]};
            unsigned bl[2] = {b_lo[h][o], b_lo[h][o + 2]};
            mma_bf16(c_[j], a_hi, bh);
            mma_bf16(c_[j], a_hi, bl);
            mma_bf16(c_[j], a_lo, bh);
        }
    }

    const int row0 = wm + (lane >> 2);
    const int coll = (lane & 3) << 1;
    #pragma unroll
    for (int j = 0; j < 4; j++) {
        int col = k0 + wn + (j << 3) + coll;
        *(unsigned*)&g_bias[((size_t)row0 << 20) + ((size_t)q << 10) + col] =
            pk_bf2(c_[j][0] * 0.125f, c_[j][1] * 0.125f);
        *(unsigned*)&g_bias[((size_t)(row0 + 8) << 20) + ((size_t)q << 10) + col] =
            pk_bf2(c_[j][2] * 0.125f, c_[j][3] * 0.125f);
    }
}

// ---------------------------------------------------------------------------
// Kernel 2: per (b, 32-row q strip). 512 threads, ~200 KB smem.
// ---------------------------------------------------------------------------
__global__ void __launch_bounds__(512) k_attn(const float* __restrict__ Q,
                                              float* attn,
                                              float* __restrict__ out)
{
    extern __shared__ float sm[];
    float* strip = sm;                                      // [32][1028]
    __nv_bfloat16* bufs = (__nv_bfloat16*)(strip + 32 * STRIP);
    __nv_bfloat16* qHi = bufs;
    __nv_bfloat16* qLo = bufs + 2048;
    __nv_bfloat16* kHi = bufs + 4096;
    __nv_bfloat16* kLo = bufs + 20480;
    __nv_bfloat16* pHi = bufs;
    __nv_bfloat16* pLo = bufs + 4096;
    __nv_bfloat16* vHi = bufs + 8192;
    __nv_bfloat16* vLo = bufs + 16384;
    float* red = (float*)bufs;
    __shared__ float sInv[32];

    const int b   = blockIdx.x;
    const int q0  = (gridDim.y - 1 - blockIdx.y) << 5;
    const int tid = threadIdx.x;
    const int warp = tid >> 5, lane = tid & 31, lhi = lane >> 4;

    {
        int r = tid >> 4, c = (tid & 15) << 2;
        float4 v = *(const float4*)&Q[((size_t)b << 16) + ((size_t)(q0 + r) << 6) + c];
        split_store(qHi, qLo, r, c, v);
    }

    const unsigned qH = (unsigned)__cvta_generic_to_shared(qHi);
    const unsigned qL = (unsigned)__cvta_generic_to_shared(qLo);
    const unsigned kH = (unsigned)__cvta_generic_to_shared(kHi);
    const unsigned kL = (unsigned)__cvta_generic_to_shared(kLo);

    // ---- phase 1: 256-wide k tiles, 16 warps = 2(m16) x 8(n32) ----
    const int wm1 = (warp & 1) << 4;
    const int wn1 = (warp >> 1) << 5;
    const int ntile1 = (q0 + 32 + 255) >> 8;

    for (int kt = 0; kt < ntile1; kt++) {
        const int k0 = kt << 8;
        const int nrow = (q0 + 32 - k0) < 256 ? (q0 + 32 - k0) : 256;  // mult of 32
        const int n16  = nrow << 3;
        __syncthreads();
        {
            const uint4* gh = (const uint4*)(g_Khi + ((size_t)b << 16) + ((size_t)k0 << 6));
            const uint4* gl = (const uint4*)(g_Klo + ((size_t)b << 16) + ((size_t)k0 << 6));
            uint4* sh = (uint4*)kHi; uint4* sl = (uint4*)kLo;
            #pragma unroll
            for (int i = 0; i < 4; i++) {
                int f = tid + (i << 9);
                if (f < n16) { sh[f] = gh[f]; sl[f] = gl[f]; }
            }
        }
        __syncthreads();

        const bool act1 = (k0 + wn1) <= (q0 + wm1 + 15);
        float c_[4][4] = {};
        if (act1) {
            const int arow = wm1 + (lane & 15);
            #pragma unroll
            for (int ks = 0; ks < 4; ks++) {
                const int cb = (ks << 1) + lhi;
                unsigned a_hi[4], a_lo[4];
                ldsm4(a_hi, qH + sw_off(arow, cb));
                ldsm4(a_lo, qL + sw_off(arow, cb));
                unsigned b_hi[2][4], b_lo[2][4];
                #pragma unroll
                for (int h = 0; h < 2; h++) {
                    int brow = wn1 + (h << 4) + (lane & 15);
                    ldsm4(b_hi[h], kH + sw_off(brow, cb));
                    ldsm4(b_lo[h], kL + sw_off(brow, cb));
                }
                #pragma unroll
                for (int j = 0; j < 4; j++) {
                    const int h = j >> 1, o = j & 1;
                    unsigned bh[2] = {b_hi[h][o], b_hi[h][o + 2]};
                    unsigned bl[2] = {b_lo[h][o], b_lo[h][o + 2]};
                    mma_bf16(c_[j], a_hi, bh);
                    mma_bf16(c_[j], a_hi, bl);
                    mma_bf16(c_[j], a_lo, bh);
                }
            }
        }
        // epilogue: scores = qk*0.125 + bias(bf16, pre-scaled), mask -> strip
        const int row0 = wm1 + (lane >> 2);
        const int coll = (lane & 3) << 1;
        if (act1) {
            #pragma unroll
            for (int j = 0; j < 4; j++) {
                int colk = k0 + wn1 + (j << 3) + coll;
                {
                    int qr = q0 + row0;
                    float2 bs = bf2f(*(const unsigned*)&g_bias[((size_t)b << 20) + ((size_t)qr << 10) + colk]);
                    float s0 = (colk     <= qr) ? fmaf(c_[j][0], 0.125f, bs.x) : 0.f;
                    float s1 = (colk + 1 <= qr) ? fmaf(c_[j][1], 0.125f, bs.y) : 0.f;
                    *(float2*)&strip[row0 * STRIP + colk] = make_float2(s0, s1);
                }
                {
                    int qr = q0 + row0 + 8;
                    float2 bs = bf2f(*(const unsigned*)&g_bias[((size_t)b << 20) + ((size_t)qr << 10) + colk]);
                    float s0 = (colk     <= qr) ? fmaf(c_[j][2], 0.125f, bs.x) : 0.f;
                    float s1 = (colk + 1 <= qr) ? fmaf(c_[j][3], 0.125f, bs.y) : 0.f;
                    *(float2*)&strip[(row0 + 8) * STRIP + colk] = make_float2(s0, s1);
                }
            }
        } else {
            #pragma unroll
            for (int j = 0; j < 4; j++) {
                int colk = k0 + wn1 + (j << 3) + coll;
                *(float2*)&strip[row0 * STRIP + colk]       = make_float2(0.f, 0.f);
                *(float2*)&strip[(row0 + 8) * STRIP + colk] = make_float2(0.f, 0.f);
            }
        }
    }
    __syncthreads();

    // ---- phase 2: softmax per row ----
    {
        const int w = warp;
        #pragma unroll
        for (int r = 0; r < 2; r++) {
            int row = (w << 1) + r;
            int qr  = q0 + row;
            float m = -1e30f;
            for (int kk = lane; kk <= qr; kk += 32)
                m = fmaxf(m, strip[row * STRIP + kk]);
            #pragma unroll
            for (int o = 16; o; o >>= 1)
                m = fmaxf(m, __shfl_xor_sync(0xffffffffu, m, o));
            float ssum = 0.f;
            for (int kk = lane; kk <= qr; kk += 32) {
                float e = fast_exp(strip[row * STRIP + kk] - m);
                strip[row * STRIP + kk] = e;
                ssum += e;
            }
            #pragma unroll
            for (int o = 16; o; o >>= 1)
                ssum += __shfl_xor_sync(0xffffffffu, ssum, o);
            if (lane == 0) sInv[row] = 1.0f / ssum;
        }
    }
    __syncthreads();

    // ---- phase 3: write normalized attn ----
    #pragma unroll
    for (int i = 0; i < 16; i++) {
        int f = tid + (i << 9);
        int row = f >> 8;
        int kc  = (f & 255) << 2;
        int qr  = q0 + row;
        float inv = sInv[row];
        float4 e = *(const float4*)&strip[row * STRIP + kc];
        float4 o;
        o.x = (kc     <= qr) ? e.x * inv : 0.f;
        o.y = (kc + 1 <= qr) ? e.y * inv : 0.f;
        o.z = (kc + 2 <= qr) ? e.z * inv : 0.f;
        o.w = (kc + 3 <= qr) ? e.w * inv : 0.f;
        *(float4*)&attn[((size_t)b << 20) + ((size_t)qr << 10) + kc] = o;
    }

    // ---- phase 4: out = P @ V.  128-wide k tiles, 16 warps = 2m x 2n x 4kg ----
    const int wm4 = (warp & 1) << 4;
    const int wn4 = ((warp >> 1) & 1) << 5;
    const int kg  = warp >> 2;
    const int ntile4 = (q0 + 32 + 127) >> 7;
    const unsigned pH = (unsigned)__cvta_generic_to_shared(pHi);
    const unsigned pL = (unsigned)__cvta_generic_to_shared(pLo);
    const unsigned vH = (unsigned)__cvta_generic_to_shared(vHi);
    const unsigned vL = (unsigned)__cvta_generic_to_shared(vLo);

    float c4[4][4] = {};

    for (int kt = 0; kt < ntile4; kt++) {
        const int k0 = kt << 7;
        const int nrow4 = (q0 + 32 - k0) < 128 ? (q0 + 32 - k0) : 128;  // mult of 32
        const int n16v  = nrow4 << 3;
        __syncthreads();
        #pragma unroll
        for (int i = 0; i < 2; i++) {
            int f = tid + (i << 9); int r = f >> 5, c = (f & 31) << 2;
            float4 v = *(const float4*)&strip[r * STRIP + k0 + c];
            int kh = c >> 6;
            split_store(pHi + (kh << 11), pLo + (kh << 11), r, c & 63, v);
        }
        {
            const uint4* gh = (const uint4*)(g_Vhi + ((size_t)b << 16) + ((size_t)k0 << 6));
            const uint4* gl = (const uint4*)(g_Vlo + ((size_t)b << 16) + ((size_t)k0 << 6));
            uint4* sh = (uint4*)vHi; uint4* sl = (uint4*)vLo;
            #pragma unroll
            for (int i = 0; i < 2; i++) {
                int f = tid + (i << 9);
                if (f < n16v) { sh[f] = gh[f]; sl[f] = gl[f]; }
            }
        }
        __syncthreads();

        const bool act4 = (k0 + (kg << 5)) <= (q0 + 31);
        if (act4) {
            const int arow = wm4 + (lane & 15);
            #pragma unroll
            for (int ks = 0; ks < 2; ks++) {
                const int ko = (kg << 5) + (ks << 4);
                const int kh = ko >> 6;
                const int cbb = (ko & 63) >> 3;
                unsigned a_hi[4], a_lo[4];
                ldsm4(a_hi, pH + (kh << 12) + sw_off(arow, cbb + lhi));
                ldsm4(a_lo, pL + (kh << 12) + sw_off(arow, cbb + lhi));
                unsigned b_hi[2][4], b_lo[2][4];
                const int brow = ko + (lane & 15);
                #pragma unroll
                for (int h = 0; h < 2; h++) {
                    int bcb = ((wn4 + (h << 4)) >> 3) + lhi;
                    ldsm4t(b_hi[h], vH + sw_off(brow, bcb));
                    ldsm4t(b_lo[h], vL + sw_off(brow, bcb));
                }
                #pragma unroll
                for (int j = 0; j < 4; j++) {
                    const int h = j >> 1, o = j & 1;
                    unsigned bh[2] = {b_hi[h][o << 1], b_hi[h][(o << 1) + 1]};
                    unsigned bl[2] = {b_lo[h][o << 1], b_lo[h][(o << 1) + 1]};
                    mma_bf16(c4[j], a_hi, bh);
                    mma_bf16(c4[j], a_hi, bl);
                    mma_bf16(c4[j], a_lo, bh);
                }
            }
        }
    }
    __syncthreads();

    const int row0 = wm4 + (lane >> 2);
    const int coll = (lane & 3) << 1;
    if (kg > 0) {
        #pragma unroll
        for (int j = 0; j < 4; j++) {
            int col = wn4 + (j << 3) + coll;
            *(float2*)&red[((kg - 1) << 11) + (row0 << 6) + col] =
                make_float2(c4[j][0], c4[j][1]);
            *(float2*)&red[((kg - 1) << 11) + ((row0 + 8) << 6) + col] =
                make_float2(c4[j][2], c4[j][3]);
        }
    }
    __syncthreads();
    if (kg == 0) {
        const float inv0 = sInv[row0];
        const float inv1 = sInv[row0 + 8];
        #pragma unroll
        for (int j = 0; j < 4; j++) {
            int col = wn4 + (j << 3) + coll;
            float2 s0 = make_float2(c4[j][0], c4[j][1]);
            float2 s1 = make_float2(c4[j][2], c4[j][3]);
            #pragma unroll
            for (int g = 0; g < 3; g++) {
                float2 p0 = *(const float2*)&red[(g << 11) + (row0 << 6) + col];
                float2 p1 = *(const float2*)&red[(g << 11) + ((row0 + 8) << 6) + col];
                s0.x += p0.x; s0.y += p0.y;
                s1.x += p1.x; s1.y += p1.y;
            }
            *(float2*)&out[((size_t)b << 16) + ((size_t)(q0 + row0) << 6) + col] =
                make_float2(s0.x * inv0, s0.y * inv0);
            *(float2*)&out[((size_t)b << 16) + ((size_t)(q0 + row0 + 8) << 6) + col] =
                make_float2(s1.x * inv1, s1.y * inv1);
        }
    }
}

// ---------------------------------------------------------------------------
// Kernel 3: out[b,q,d] += sum_k attn[b,q,k] * R_v[q,k,d]   (unchanged)
// ---------------------------------------------------------------------------
__global__ void __launch_bounds__(256) k_rv(const float* __restrict__ attn,
                                            const float* __restrict__ Rv,
                                            float* __restrict__ out)
{
    const int q   = 1023 - blockIdx.x;
    const int tid = threadIdx.x;
    const int ntile = (q >> 6) + 1;

    __shared__ __align__(16) __nv_bfloat16 aHi[4096], aLo[4096], bHi[4096], bLo[4096];

    const int warp = tid >> 5, lane = tid & 31;
    const int wm = (warp & 3) << 4;
    const int wn = (warp >> 2) << 5;

    const unsigned aH = (unsigned)__cvta_generic_to_shared(aHi);
    const unsigned aL = (unsigned)__cvta_generic_to_shared(aLo);
    const unsigned bH = (unsigned)__cvta_generic_to_shared(bHi);
    const unsigned bL = (unsigned)__cvta_generic_to_shared(bLo);

    const int arow = wm + (lane & 15);
    const int lhi  = lane >> 4;

    float c_[4][4] = {};

    for (int kt = 0; kt < ntile; kt++) {
        const int k0 = kt << 6;
        __syncthreads();
        #pragma unroll
        for (int i = 0; i < 4; i++) {
            int f = tid + (i << 8); int r = f >> 4, c = (f & 15) << 2;
            float4 v = *(const float4*)&attn[((size_t)r << 20) + ((size_t)q << 10) + (size_t)(k0 + c)];
            split_store(aHi, aLo, r, c, v);
        }
        #pragma unroll
        for (int i = 0; i < 4; i++) {
            int f = tid + (i << 8); int r = f >> 4, c = (f & 15) << 2;
            float4 v = *(const float4*)&Rv[(((size_t)q << 10) + (size_t)(k0 + r)) * 64 + c];
            split_store(bHi, bLo, r, c, v);
        }
        __syncthreads();

        #pragma unroll
        for (int ks = 0; ks < 4; ks++) {
            const int cb = (ks << 1) + lhi;
            unsigned a_hi[4], a_lo[4];
            ldsm4(a_hi, aH + sw_off(arow, cb));
            ldsm4(a_lo, aL + sw_off(arow, cb));
            unsigned b_hi[2][4], b_lo[2][4];
            #pragma unroll
            for (int h = 0; h < 2; h++) {
                int brow = (ks << 4) + (lane & 15);
                int bcb  = ((wn + (h << 4)) >> 3) + lhi;
                ldsm4t(b_hi[h], bH + sw_off(brow, bcb));
                ldsm4t(b_lo[h], bL + sw_off(brow, bcb));
            }
            #pragma unroll
            for (int j = 0; j < 4; j++) {
                const int h = j >> 1, o = j & 1;
                unsigned bh[2] = {b_hi[h][o << 1], b_hi[h][(o << 1) + 1]};
                unsigned bl[2] = {b_lo[h][o << 1], b_lo[h][(o << 1) + 1]};
                mma_bf16(c_[j], a_hi, bh);
                mma_bf16(c_[j], a_hi, bl);
                mma_bf16(c_[j], a_lo, bh);
            }
        }
    }

    const int row0 = wm + (lane >> 2);
    const int coll = (lane & 3) << 1;
    #pragma unroll
    for (int j = 0; j < 4; j++) {
        int col = wn + (j << 3) + coll;
        {
            float2* p = (float2*)&out[((size_t)row0 << 16) + ((size_t)q << 6) + col];
            float2 o = *p; o.x += c_[j][0]; o.y += c_[j][1]; *p = o;
        }
        {
            float2* p = (float2*)&out[((size_t)(row0 + 8) << 16) + ((size_t)q << 6) + col];
            float2 o = *p; o.x += c_[j][2]; o.y += c_[j][3]; *p = o;
        }
    }
}

// ---------------------------------------------------------------------------
extern "C" void kernel_launch(void* const* d_in, const int* in_sizes, int n_in,
                              void* d_out, int out_size)
{
    const float* Q  = (const float*)d_in[0];
    const float* K  = (const float*)d_in[1];
    const float* V  = (const float*)d_in[2];
    const float* Rk = (const float*)d_in[3];
    const float* Rv = (const float*)d_in[4];
    float* out  = (float*)d_out;
    float* attn = out + SZ_OUT;

    const int smem2 = 32 * STRIP * (int)sizeof(float) + 36864 * (int)sizeof(__nv_bfloat16);
    cudaFuncSetAttribute(k_attn, cudaFuncAttributeMaxDynamicSharedMemorySize, smem2);

    k_prep<<<dim3(64, 8), 256>>>(K, V);
    k_bias<<<dim3(16, 1024), 256>>>(Q, Rk);
    k_attn<<<dim3(64, 32), 512, smem2>>>(Q, attn, out);
    k_rv<<<1024, 256>>>(attn, Rv, out);
}